// round 12
// baseline (speedup 1.0000x reference)
#include <cuda_runtime.h>
#include <cstdint>

// Model_PDE_2: N=131072, H=1024, D=2.  tf32 mma.sync, R11:
// - H-split: CTA (ptile, half) does 128 points x 512 h (14.5KB smem, high occ)
// - no setup kernel: derived weights computed inline while staging smem;
//   C0/C1 eliminated via u = 1 - t^2 accumulated directly.
//
//   per (n,h): z = x0*a+x1*b+c; t = tanh(z); u = 1-t^2; t3 = t*u
//   D[32pts x 8] += A * B sparse:
//     col0: out = sum t*w ; col1: g0 = sum u*wa ; col2: g1 = sum u*wb
//     col3: dx = sum t3*wbb   (wbb = -2*w*b^2)
//   pde = .5*x1^2 + g0 + .5*dx + .5*x1*g1 - (.25/3.6)*g1^2
// Output: d_out[0..N)=out, d_out[N..2N)=pde.

#define HID 1024
#define HHALF 512
#define TPB 128
#define NTRI_H (HHALF / 8)  // 64 triples per half
#define WT_STRIDE 520       // rows offset by 8 banks -> conflict-free
#define NMAX 131072

__device__ float2 g_pA[2 * NMAX];  // per-half partials {out, g0}
__device__ float2 g_pB[2 * NMAX];  // per-half partials {g1, dx}

__device__ __forceinline__ float tanh_fast(float z) {
    float t;
    asm("tanh.approx.f32 %0, %1;" : "=f"(t) : "f"(z));
    return t;
}

__device__ __forceinline__ void mma_tf32(float* d, float a0, float a1, float a2,
                                         float a3, float b0, float b1) {
    asm volatile(
        "mma.sync.aligned.m16n8k8.row.col.f32.tf32.tf32.f32 "
        "{%0,%1,%2,%3}, {%4,%5,%6,%7}, {%8,%9}, {%0,%1,%2,%3};"
        : "+f"(d[0]), "+f"(d[1]), "+f"(d[2]), "+f"(d[3])
        : "r"(__float_as_uint(a0)), "r"(__float_as_uint(a1)),
          "r"(__float_as_uint(a2)), "r"(__float_as_uint(a3)),
          "r"(__float_as_uint(b0)), "r"(__float_as_uint(b1)));
}

__global__ __launch_bounds__(TPB) void pde_main(const float* __restrict__ x,
                                                const float* __restrict__ W1,
                                                const float* __restrict__ b1,
                                                const float* __restrict__ w2,
                                                int N) {
    __shared__ float2 s_ab[HHALF];          // 4 KB
    __shared__ float s_cc[HHALF];           // 2 KB
    __shared__ float s_wt[4 * WT_STRIDE];   // 8.3 KB

    int tid = threadIdx.x;
    int half = blockIdx.x & 1;
    int ptile = blockIdx.x >> 1;
    int hoff = half * HHALF;

    // Stage + derive weights inline (W1/b1/w2 slice is L2-resident).
    for (int i = tid; i < HHALF; i += TPB) {
        int h = hoff + i;
        float2 ab = reinterpret_cast<const float2*>(W1)[h];
        float c = b1[h];
        float w = w2[h];
        s_ab[i] = ab;
        s_cc[i] = c;
        s_wt[0 * WT_STRIDE + i] = w;                       // w
        s_wt[1 * WT_STRIDE + i] = w * ab.x;                // wa
        s_wt[2 * WT_STRIDE + i] = w * ab.y;                // wb
        s_wt[3 * WT_STRIDE + i] = -2.0f * w * ab.y * ab.y; // wbb
    }
    __syncthreads();

    int lane = tid & 31;
    int wid = tid >> 5;
    int g = lane >> 2;   // group id = output column n, also row base
    int tig = lane & 3;  // thread-in-group = k sub-col
    int n = g;
    // Octet in which this column's B entry is nonzero:
    // n=0 (w, t): j=0 ; n=1,2 (wa,wb with u): j=1 ; n=3 (wbb, t3): j=2
    int jn = (n == 0) ? 0 : (n <= 2) ? 1 : (n == 3) ? 2 : -1;
    bool has_b = (n < 4);
    const float* wtp = s_wt + (n & 3) * WT_STRIDE;

    int base_pt = ptile * TPB + wid * 32;

    float2 myx = reinterpret_cast<const float2*>(x)[base_pt + lane];
    float x0r[4], x1r[4];
#pragma unroll
    for (int i = 0; i < 4; i++) {
        x0r[i] = __shfl_sync(0xffffffffu, myx.x, g + 8 * i);
        x1r[i] = __shfl_sync(0xffffffffu, myx.y, g + 8 * i);
    }

    float acc0[4] = {0.f, 0.f, 0.f, 0.f};  // rows g, g+8
    float acc1[4] = {0.f, 0.f, 0.f, 0.f};  // rows g+16, g+24

#pragma unroll 2
    for (int tr = 0; tr < NTRI_H; tr++) {
        int h0 = tr * 8 + tig;
        int h1 = h0 + 4;
        float2 ab0 = s_ab[h0];
        float2 ab1 = s_ab[h1];
        float cc0 = s_cc[h0];
        float cc1 = s_cc[h1];
        float w0 = 0.f, w1 = 0.f;
        if (has_b) {
            w0 = wtp[h0];
            w1 = wtp[h1];
        }

        // Stage 1: t -> mma octet 0
        float t[4][2];
#pragma unroll
        for (int r = 0; r < 4; r++) {
            float z0 = __fmaf_rn(x1r[r], ab0.y, __fmaf_rn(x0r[r], ab0.x, cc0));
            t[r][0] = tanh_fast(z0);
            float z1 = __fmaf_rn(x1r[r], ab1.y, __fmaf_rn(x0r[r], ab1.x, cc1));
            t[r][1] = tanh_fast(z1);
        }
        {
            float b0 = (jn == 0) ? w0 : 0.f;
            float b1 = (jn == 0) ? w1 : 0.f;
            mma_tf32(acc0, t[0][0], t[1][0], t[0][1], t[1][1], b0, b1);
            mma_tf32(acc1, t[2][0], t[3][0], t[2][1], t[3][1], b0, b1);
        }
        // Stage 2: u = 1 - t^2 -> mma octet 1
        float u[4][2];
#pragma unroll
        for (int r = 0; r < 4; r++) {
            u[r][0] = __fmaf_rn(-t[r][0], t[r][0], 1.0f);
            u[r][1] = __fmaf_rn(-t[r][1], t[r][1], 1.0f);
        }
        {
            float b0 = (jn == 1) ? w0 : 0.f;
            float b1 = (jn == 1) ? w1 : 0.f;
            mma_tf32(acc0, u[0][0], u[1][0], u[0][1], u[1][1], b0, b1);
            mma_tf32(acc1, u[2][0], u[3][0], u[2][1], u[3][1], b0, b1);
        }
        // Stage 3: t3 = t * u (in place) -> mma octet 2
#pragma unroll
        for (int r = 0; r < 4; r++) {
            t[r][0] = t[r][0] * u[r][0];
            t[r][1] = t[r][1] * u[r][1];
        }
        {
            float b0 = (jn == 2) ? w0 : 0.f;
            float b1 = (jn == 2) ? w1 : 0.f;
            mma_tf32(acc0, t[0][0], t[1][0], t[0][1], t[1][1], b0, b1);
            mma_tf32(acc1, t[2][0], t[3][0], t[2][1], t[3][1], b0, b1);
        }
    }

    // Partial store: tig0 holds cols {0,1} = {out, g0}; tig1 holds {2,3} = {g1, dx}.
    int sbase = half * NMAX + base_pt + g;
    if (tig == 0) {
        g_pA[sbase + 0] = make_float2(acc0[0], acc0[1]);
        g_pA[sbase + 8] = make_float2(acc0[2], acc0[3]);
        g_pA[sbase + 16] = make_float2(acc1[0], acc1[1]);
        g_pA[sbase + 24] = make_float2(acc1[2], acc1[3]);
    } else if (tig == 1) {
        g_pB[sbase + 0] = make_float2(acc0[0], acc0[1]);
        g_pB[sbase + 8] = make_float2(acc0[2], acc0[3]);
        g_pB[sbase + 16] = make_float2(acc1[0], acc1[1]);
        g_pB[sbase + 24] = make_float2(acc1[2], acc1[3]);
    }
}

__global__ __launch_bounds__(256) void pde_epilogue(const float* __restrict__ x,
                                                    const float* __restrict__ b2,
                                                    float* __restrict__ out,
                                                    int N) {
    int p = blockIdx.x * 256 + threadIdx.x;
    if (p >= N) return;

    float2 a0 = g_pA[p];
    float2 a1 = g_pA[NMAX + p];
    float2 bb0 = g_pB[p];
    float2 bb1 = g_pB[NMAX + p];
    float2 xv = reinterpret_cast<const float2*>(x)[p];
    float x1 = xv.y;

    float ov = a0.x + a1.x;
    float g0 = a0.y + a1.y;
    float g1 = bb0.x + bb1.x;
    float dx = bb0.y + bb1.y;

    float pde = __fmaf_rn(0.5f * x1, x1, g0);
    pde = __fmaf_rn(0.5f, dx, pde);
    pde = __fmaf_rn(0.5f * x1, g1, pde);
    pde = __fmaf_rn(-0.069444444444444444f * g1, g1, pde);

    out[p] = ov + b2[0];
    out[N + p] = pde;
}

extern "C" void kernel_launch(void* const* d_in, const int* in_sizes, int n_in,
                              void* d_out, int out_size) {
    const float* x = (const float*)d_in[0];
    const float* W1 = (const float*)d_in[1];
    const float* b1 = (const float*)d_in[2];
    const float* w2 = (const float*)d_in[3];
    const float* b2 = (const float*)d_in[4];
    int N = in_sizes[0] / 2;

    pde_main<<<(N / TPB) * 2, TPB>>>(x, W1, b1, w2, N);
    pde_epilogue<<<(N + 255) / 256, 256>>>(x, b2, (float*)d_out, N);
}